// round 10
// baseline (speedup 1.0000x reference)
#include <cuda_runtime.h>
#include <math.h>
#include <stdint.h>

#define Kk 256
#define Tt 512
#define NBb 256
#define Vv 4096

#define NT 256
#define NC (NBb/2)      // 128 CTAs, 2 sequences each

// Warp tiling: 8 warps = 2 (p) x 4 (q). Warp (p,q): output states
// {128p+32m+lane, m=0..3}, summation i in [64q,64q+64).
// Per thread: 4 states x 64 i = 128 u64 pairs; 72 in regs, 56 via smem.
// Single barrier per step: each warp redundantly computes the tail for
// state-slice q (= its own e-slice), keeps es warp-private.

typedef unsigned long long ull;

// ---------------- device scratch ----------------
__device__ ull  g_Freg[72*NT];     // forward  A-pack, register part
__device__ ull  g_Fsm [56*NT];     // forward  A-pack, smem part
__device__ ull  g_Breg[72*NT];     // backward A-pack, register part
__device__ ull  g_Bsm [56*NT];     // backward A-pack, smem part
__device__ float g_Bt[Vv*Kk];      // exp(log_B) transposed: [v][j]
__device__ float g_pi[Kk];

// ---------------- prep ----------------
__global__ void prep_pack(const float* __restrict__ logA, const float* __restrict__ logpi) {
    int idx = blockIdx.x * blockDim.x + threadIdx.x;   // 0 .. 32767
    if (idx < Kk) g_pi[idx] = expf(logpi[idx]);
    int tid = idx & 255;
    int k   = idx >> 8;            // 0..127 : k = m*32 + c
    int m = k >> 5, c = k & 31;
    int wi = tid >> 5, l = tid & 31;
    int p = wi >> 2, q = wi & 3;
    int j = 128*p + 32*m + l;      // output state
    int i = 64*q + 2*c;            // summation index (pair base)
    float f0 = expf(logA[i*Kk + j]);        // fwd: sum_i e[i]*A[i][j]
    float f1 = expf(logA[(i+1)*Kk + j]);
    float b0 = expf(logA[j*Kk + i]);        // bwd: sum_i e[i]*A[j][i]
    float b1 = expf(logA[j*Kk + i + 1]);
    ull fv = ((ull)__float_as_uint(f1) << 32) | __float_as_uint(f0);
    ull bv = ((ull)__float_as_uint(b1) << 32) | __float_as_uint(b0);
    if (c < 18) {
        g_Freg[(m*18 + c)*NT + tid] = fv;
        g_Breg[(m*18 + c)*NT + tid] = bv;
    } else {
        int cc = c - 18;
        int u = (((m*7 + (cc>>1))*NT + tid) << 1) | (cc & 1);  // ulonglong2-friendly
        g_Fsm[u] = fv;
        g_Bsm[u] = bv;
    }
}

__global__ void prep_B(const float* __restrict__ logB) {
    int idx = blockIdx.x * blockDim.x + threadIdx.x;   // j*Vv + v (coalesced read)
    if (idx >= Kk*Vv) return;
    int j = idx / Vv, v = idx % Vv;
    g_Bt[v*Kk + j] = expf(logB[idx]);
}

// ---------------- helpers ----------------
__device__ __forceinline__ void ffma2(ull& d, ull a, ull b) {
    asm("fma.rn.f32x2 %0, %1, %2, %0;" : "+l"(d) : "l"(a), "l"(b));
}
__device__ __forceinline__ float psum1(ull a) {
    unsigned lo, hi; asm("mov.b64 {%0,%1}, %2;" : "=r"(lo), "=r"(hi) : "l"(a));
    return __uint_as_float(lo) + __uint_as_float(hi);
}
__device__ __forceinline__ float wred1(float v) {
    #pragma unroll
    for (int o = 16; o; o >>= 1) v += __shfl_xor_sync(0xFFFFFFFFu, v, o);
    return v;
}

// split-K dot: warp covers i in [64q,64q+64) (warp-private e-slice) for its
// 4 states x 2 seqs; writes partials for the NEXT buffer.
__device__ __forceinline__ void do_dot(const ull (&ra)[72],
                                       const ull* __restrict__ As2,
                                       const float* __restrict__ esw,  // [2][64] private
                                       float* __restrict__ partw,      // [4k][2seq][256j]
                                       int p, int q, int l, int tid) {
    const ulonglong2* e0 = reinterpret_cast<const ulonglong2*>(esw);
    const ulonglong2* e1 = reinterpret_cast<const ulonglong2*>(esw + 64);
    ull acc[4][2] = {};
    // register half: e pairs 0..17 (ulonglong2 0..8)
    #pragma unroll
    for (int h = 0; h < 9; h++) {
        ulonglong2 v0 = e0[h], v1 = e1[h];
        #pragma unroll
        for (int m = 0; m < 4; m++) {
            ffma2(acc[m][0], ra[m*18 + 2*h],     v0.x);
            ffma2(acc[m][0], ra[m*18 + 2*h + 1], v0.y);
            ffma2(acc[m][1], ra[m*18 + 2*h],     v1.x);
            ffma2(acc[m][1], ra[m*18 + 2*h + 1], v1.y);
        }
    }
    // smem half: e pairs 18..31 (ulonglong2 9..15)
    const ulonglong2* Asv = reinterpret_cast<const ulonglong2*>(As2);
    #pragma unroll
    for (int h = 0; h < 7; h++) {
        ulonglong2 v0 = e0[9 + h], v1 = e1[9 + h];
        #pragma unroll
        for (int m = 0; m < 4; m++) {
            ulonglong2 av = Asv[(m*7 + h)*NT + tid];
            ffma2(acc[m][0], av.x, v0.x);
            ffma2(acc[m][0], av.y, v0.y);
            ffma2(acc[m][1], av.x, v1.x);
            ffma2(acc[m][1], av.y, v1.y);
        }
    }
    #pragma unroll
    for (int m = 0; m < 4; m++) {
        int j = 128*p + 32*m + l;
        partw[(q*2    )*256 + j] = psum1(acc[m][0]);
        partw[(q*2 + 1)*256 + j] = psum1(acc[m][1]);
    }
}

// ---------------- main persistent kernel ----------------
__global__ void __launch_bounds__(NT, 1)
hmm_fb(const int* __restrict__ obs, float* __restrict__ out) {
    extern __shared__ float sm[];
    ull*   As2   = (ull*)sm;                    // 56*NT u64 = 112KB
    float* esAll = (float*)(As2 + 56*NT);       // 8 warps x [2][64]
    float* part  = esAll + 8*128;               // [2 buf][4k][2seq][256]
    float* ssum  = part + 2*2048;               // [2 buf][2seq][4q]
    int*   obs_s = (int*)(ssum + 16);           // [2][Tt]

    const int tid = threadIdx.x, wi = tid >> 5, l = tid & 31;
    const int p = wi >> 2, q = wi & 3;
    const int n0 = 2*blockIdx.x, n1 = n0 + 1;
    const int j0 = 64*q + l, j1 = j0 + 32;

    for (int i = tid; i < Tt; i += NT) {
        obs_s[i]      = obs[n0*Tt + i];
        obs_s[Tt + i] = obs[n1*Tt + i];
    }

    ull ra[72];
    #pragma unroll
    for (int k = 0; k < 72; k++) ra[k] = g_Freg[k*NT + tid];
    {
        const ulonglong2* src = reinterpret_cast<const ulonglong2*>(g_Fsm);
        ulonglong2*       dst = reinterpret_cast<ulonglong2*>(As2);
        #pragma unroll
        for (int k = 0; k < 28; k++) dst[k*NT + tid] = src[k*NT + tid];
    }

    // init buffer 0: u == pi, r == 1  ->  w_0 = pi * bb_0
    {
        float pi = g_pi[tid];
        #pragma unroll
        for (int k = 0; k < 4; k++) {
            part[(k*2    )*256 + tid] = (k == 0) ? pi : 0.f;
            part[(k*2 + 1)*256 + tid] = (k == 0) ? pi : 0.f;
        }
        if (tid < 8) ssum[tid] = ((tid & 3) == 0) ? 1.f : 0.f;
    }

    float* esw  = esAll + wi*128;
    float* outp = out + (size_t)(p ? n1 : n0)*Tt*Kk;
    int b = 0;

    // bb prefetch for t = 0
    float bn00 = g_Bt[obs_s[0]*Kk  + j0], bn01 = g_Bt[obs_s[0]*Kk  + j1];
    float bn10 = g_Bt[obs_s[Tt]*Kk + j0], bn11 = g_Bt[obs_s[Tt]*Kk + j1];

    // ---- forward ----
    for (int t = 0; t < Tt; t++) {
        __syncthreads();                         // part[b], ssum[b] published
        float b00 = bn00, b01 = bn01, b10 = bn10, b11 = bn11;
        if (t < Tt-1) {                          // prefetch bb for t+1 (hidden)
            int on0 = obs_s[t+1], on1 = obs_s[Tt + t + 1];
            bn00 = g_Bt[on0*Kk + j0]; bn01 = g_Bt[on0*Kk + j1];
            bn10 = g_Bt[on1*Kk + j0]; bn11 = g_Bt[on1*Kk + j1];
        }
        const float* pb = part + b*2048;
        const float* sb = ssum + b*8;
        float r0 = __fdividef(1.f, (sb[0] + sb[1]) + (sb[2] + sb[3]));
        float r1 = __fdividef(1.f, (sb[4] + sb[5]) + (sb[6] + sb[7]));
        float u00 = 0.f, u01 = 0.f, u10 = 0.f, u11 = 0.f;
        #pragma unroll
        for (int k = 0; k < 4; k++) {
            u00 += pb[(k*2)*256 + j0];     u01 += pb[(k*2)*256 + j1];
            u10 += pb[(k*2 + 1)*256 + j0]; u11 += pb[(k*2 + 1)*256 + j1];
        }
        float w00 = u00*r0*b00, w01 = u01*r0*b01;
        float w10 = u10*r1*b10, w11 = u11*r1*b11;
        // store raw w for my seq (per-row scale is free; epilogue renormalizes)
        outp[(size_t)t*Kk + j0] = p ? w10 : w00;
        outp[(size_t)t*Kk + j1] = p ? w11 : w01;
        if (t < Tt-1) {
            esw[l]      = w00; esw[32 + l] = w01;
            esw[64 + l] = w10; esw[96 + l] = w11;
            float sp = wred1(p ? (w10 + w11) : (w00 + w01));
            if (!l) ssum[(b^1)*8 + p*4 + q] = sp;
            __syncwarp();
            do_dot(ra, As2, esw, part + (b^1)*2048, p, q, l, tid);
            b ^= 1;
        }
    }
    __syncthreads();

    // ---- reload A-pack for backward ----
    #pragma unroll
    for (int k = 0; k < 72; k++) ra[k] = g_Breg[k*NT + tid];
    {
        const ulonglong2* src = reinterpret_cast<const ulonglong2*>(g_Bsm);
        ulonglong2*       dst = reinterpret_cast<ulonglong2*>(As2);
        #pragma unroll
        for (int k = 0; k < 28; k++) dst[k*NT + tid] = src[k*NT + tid];
    }
    // init buffer 0: u == 1, r == 1  ->  beta_{T-1} = 1
    {
        #pragma unroll
        for (int k = 0; k < 4; k++) {
            part[(k*2    )*256 + tid] = (k == 0) ? 1.f : 0.f;
            part[(k*2 + 1)*256 + tid] = (k == 0) ? 1.f : 0.f;
        }
        if (tid < 8) ssum[tid] = ((tid & 3) == 0) ? 1.f : 0.f;
    }
    b = 0;
    // prefetch p-row and bb for t = Tt-1
    float pp0 = outp[(size_t)(Tt-1)*Kk + j0];
    float pp1 = outp[(size_t)(Tt-1)*Kk + j1];
    bn00 = g_Bt[obs_s[Tt-1]*Kk      + j0]; bn01 = g_Bt[obs_s[Tt-1]*Kk      + j1];
    bn10 = g_Bt[obs_s[Tt + Tt-1]*Kk + j0]; bn11 = g_Bt[obs_s[Tt + Tt-1]*Kk + j1];

    // ---- backward ----
    for (int t = Tt - 1; t >= 0; t--) {
        __syncthreads();
        float b00 = bn00, b01 = bn01, b10 = bn10, b11 = bn11;
        float q0 = pp0, q1 = pp1;
        if (t > 0) {                             // prefetch for t-1 (hidden)
            pp0 = outp[(size_t)(t-1)*Kk + j0];
            pp1 = outp[(size_t)(t-1)*Kk + j1];
            int on0 = obs_s[t-1], on1 = obs_s[Tt + t - 1];
            bn00 = g_Bt[on0*Kk + j0]; bn01 = g_Bt[on0*Kk + j1];
            bn10 = g_Bt[on1*Kk + j0]; bn11 = g_Bt[on1*Kk + j1];
        }
        const float* pb = part + b*2048;
        const float* sb = ssum + b*8;
        float r0 = __fdividef(1.f, (sb[0] + sb[1]) + (sb[2] + sb[3]));
        float r1 = __fdividef(1.f, (sb[4] + sb[5]) + (sb[6] + sb[7]));
        float u00 = 0.f, u01 = 0.f, u10 = 0.f, u11 = 0.f;
        #pragma unroll
        for (int k = 0; k < 4; k++) {
            u00 += pb[(k*2)*256 + j0];     u01 += pb[(k*2)*256 + j1];
            u10 += pb[(k*2 + 1)*256 + j0]; u11 += pb[(k*2 + 1)*256 + j1];
        }
        float e00 = u00*r0, e01 = u01*r0;        // scaled beta_t
        float e10 = u10*r1, e11 = u11*r1;
        // gamma (unnormalized) for my seq
        outp[(size_t)t*Kk + j0] = q0 * (p ? e10 : e00);
        outp[(size_t)t*Kk + j1] = q1 * (p ? e11 : e01);
        if (t > 0) {
            float y00 = e00*b00, y01 = e01*b01;  // y_t = bb_t . beta_t
            float y10 = e10*b10, y11 = e11*b11;
            esw[l]      = y00; esw[32 + l] = y01;
            esw[64 + l] = y10; esw[96 + l] = y11;
            float sp = wred1(p ? (y10 + y11) : (y00 + y01));
            if (!l) ssum[(b^1)*8 + p*4 + q] = sp;
            __syncwarp();
            do_dot(ra, As2, esw, part + (b^1)*2048, p, q, l, tid);
            b ^= 1;
        }
    }
}

// ---------------- epilogue: per-(n,t) log-normalize ----------------
__global__ void __launch_bounds__(256)
norm_gamma(float* __restrict__ out) {
    int row  = (blockIdx.x << 3) + (threadIdx.x >> 5);
    int lane = threadIdx.x & 31;
    float4* p = reinterpret_cast<float4*>(out + (size_t)row * Kk);
    float4 v0 = p[lane], v1 = p[lane + 32];
    float s = v0.x + v0.y + v0.z + v0.w + v1.x + v1.y + v1.z + v1.w;
    #pragma unroll
    for (int o = 16; o; o >>= 1) s += __shfl_xor_sync(0xFFFFFFFFu, s, o);
    float lc = __logf(s);
    v0.x = __logf(v0.x) - lc; v0.y = __logf(v0.y) - lc;
    v0.z = __logf(v0.z) - lc; v0.w = __logf(v0.w) - lc;
    v1.x = __logf(v1.x) - lc; v1.y = __logf(v1.y) - lc;
    v1.z = __logf(v1.z) - lc; v1.w = __logf(v1.w) - lc;
    p[lane] = v0; p[lane + 32] = v1;
}

// ---------------- launch ----------------
extern "C" void kernel_launch(void* const* d_in, const int* in_sizes, int n_in,
                              void* d_out, int out_size) {
    const float* log_pi = (const float*)d_in[0];
    const float* log_A  = (const float*)d_in[1];
    const float* log_B  = (const float*)d_in[2];
    const int*   observ = (const int*)  d_in[3];
    float* out = (float*)d_out;

    const int smem_bytes = 56*NT*8 + (8*128 + 2*2048 + 16)*4 + 2*Tt*4;
    cudaFuncSetAttribute(hmm_fb, cudaFuncAttributeMaxDynamicSharedMemorySize, smem_bytes);

    prep_pack<<<128, 256>>>(log_A, log_pi);
    prep_B<<<(Kk*Vv + 255)/256, 256>>>(log_B);
    hmm_fb<<<NC, NT, smem_bytes>>>(observ, out);
    norm_gamma<<<(NBb*Tt)/8, 256>>>(out);
}